// round 12
// baseline (speedup 1.0000x reference)
#include <cuda_runtime.h>
#include <cuda_fp16.h>
#include <cuda_bf16.h>
#include <cstdint>

#define N_NODES_MAX 100000
#define E_MAX 1600000
#define IN_F 128
#define OUT_F 64
#define NDIV 9
#define CAT_F (NDIV * OUT_F)   // 576
#define DPB 3                  // divisions per block (GEMM)
#define NB_MAX (N_NODES_MAX * NDIV)   // 900000 buckets

// Scratch (static device globals: allowed)
__device__ __half  g_Whh[(size_t)NDIV * N_NODES_MAX * OUT_F];  // 115.2 MB
__device__ int     g_hist[NB_MAX];
__device__ int     g_offs[NB_MAX + 1];
__device__ int     g_cursor[NB_MAX];
__device__ int     g_bsums[1024];
__device__ int     g_meta[E_MAX];      // src node per sorted edge slot

// ---------------------------------------------------------------------------
// bf16 split helpers
// ---------------------------------------------------------------------------
__device__ __forceinline__ unsigned bf16bits(float x) {
    __nv_bfloat16 h = __float2bfloat16(x);
    return (unsigned)__bfloat16_as_ushort(h);
}
__device__ __forceinline__ void split_pair(float x0, float x1,
                                           unsigned& hw, unsigned& lw) {
    unsigned h0 = bf16bits(x0), h1 = bf16bits(x1);
    float r0 = x0 - __uint_as_float(h0 << 16);
    float r1 = x1 - __uint_as_float(h1 << 16);
    unsigned l0 = bf16bits(r0), l1 = bf16bits(r1);
    hw = h0 | (h1 << 16);
    lw = l0 | (l1 << 16);
}

__device__ __forceinline__ void mma_bf16(float c[4],
                                         unsigned a0, unsigned a1, unsigned a2, unsigned a3,
                                         unsigned b0, unsigned b1) {
    asm volatile(
        "mma.sync.aligned.m16n8k16.row.col.f32.bf16.bf16.f32 "
        "{%0,%1,%2,%3}, {%4,%5,%6,%7}, {%8,%9}, {%0,%1,%2,%3};"
        : "+f"(c[0]), "+f"(c[1]), "+f"(c[2]), "+f"(c[3])
        : "r"(a0), "r"(a1), "r"(a2), "r"(a3), "r"(b0), "r"(b1));
}

// Fragment-packed smem layout: per row, k-chunk kc, pair u_local:
// slot = (u&3)*4 + (u>>2) -> hi word; slot+2 -> lo word; word = kc*16+slot.
#define ROW_W 144
#define A_WORDS (128 * ROW_W)
#define B_WORDS (64 * ROW_W)
#define GEMM_SMEM_BYTES ((A_WORDS + B_WORDS) * 4)   // 110,592 B

__device__ __forceinline__ int slot_of(int u_local) {
    return (u_local & 3) * 4 + (u_local >> 2);
}

__global__ __launch_bounds__(256, 2)
void gemm_kernel(const float* __restrict__ feature,
                 const float* __restrict__ norm,
                 const float* __restrict__ W,
                 int n_nodes) {
    extern __shared__ unsigned smw[];
    unsigned* As = smw;             // [128][ROW_W]
    unsigned* Bs = smw + A_WORDS;   // [64][ROW_W]

    const int row0 = blockIdx.x * 128;
    const int d0   = blockIdx.y * DPB;
    const int tid  = threadIdx.x;

    for (int i = tid; i < 128 * 32; i += 256) {
        int r = i >> 5, c4 = i & 31;
        float4 v = make_float4(0.f, 0.f, 0.f, 0.f);
        int gr = row0 + r;
        if (gr < n_nodes)
            v = *(const float4*)(feature + (size_t)gr * IN_F + c4 * 4);
        unsigned* rowp = As + r * ROW_W;
        int u0 = c4 * 2;
        unsigned hw, lw;
        split_pair(v.x, v.y, hw, lw);
        int s0 = (u0 >> 3) * 16 + slot_of(u0 & 7);
        rowp[s0] = hw; rowp[s0 + 2] = lw;
        int u1 = u0 + 1;
        split_pair(v.z, v.w, hw, lw);
        int s1 = (u1 >> 3) * 16 + slot_of(u1 & 7);
        rowp[s1] = hw; rowp[s1 + 2] = lw;
    }

    const int warp = tid >> 5, lane = tid & 31;
    const int g = lane >> 2, t = lane & 3;
    const int m0 = warp * 16;
    const int r0 = row0 + m0 + g;
    const int r1 = r0 + 8;
    const float s0n = (r0 < n_nodes) ? __ldg(norm + r0) : 0.f;
    const float s1n = (r1 < n_nodes) ? __ldg(norm + r1) : 0.f;

    for (int dd = 0; dd < DPB; dd++) {
        const int d = d0 + dd;
        __syncthreads();
        for (int i = tid; i < 64 * 32; i += 256) {
            int r = i >> 5, c4 = i & 31;
            float4 v = *(const float4*)(W + ((size_t)d * OUT_F + r) * IN_F + c4 * 4);
            unsigned* rowp = Bs + r * ROW_W;
            int u0 = c4 * 2;
            unsigned hw, lw;
            split_pair(v.x, v.y, hw, lw);
            int s0 = (u0 >> 3) * 16 + slot_of(u0 & 7);
            rowp[s0] = hw; rowp[s0 + 2] = lw;
            int u1 = u0 + 1;
            split_pair(v.z, v.w, hw, lw);
            int s1 = (u1 >> 3) * 16 + slot_of(u1 & 7);
            rowp[s1] = hw; rowp[s1 + 2] = lw;
        }
        __syncthreads();

        float acc[8][4];
#pragma unroll
        for (int nt = 0; nt < 8; nt++)
            acc[nt][0] = acc[nt][1] = acc[nt][2] = acc[nt][3] = 0.f;

#pragma unroll
        for (int kc = 0; kc < 8; kc++) {
            const int off = kc * 16 + 4 * t;
            uint4 ag  = *(const uint4*)(As + (m0 + g)     * ROW_W + off);
            uint4 ag8 = *(const uint4*)(As + (m0 + g + 8) * ROW_W + off);
            uint4 b[8];
#pragma unroll
            for (int nt = 0; nt < 8; nt++)
                b[nt] = *(const uint4*)(Bs + (nt * 8 + g) * ROW_W + off);
#pragma unroll
            for (int nt = 0; nt < 8; nt++)
                mma_bf16(acc[nt], ag.x, ag8.x, ag.y, ag8.y, b[nt].x, b[nt].y);
#pragma unroll
            for (int nt = 0; nt < 8; nt++)
                mma_bf16(acc[nt], ag.x, ag8.x, ag.y, ag8.y, b[nt].z, b[nt].w);
#pragma unroll
            for (int nt = 0; nt < 8; nt++)
                mma_bf16(acc[nt], ag.z, ag8.z, ag.w, ag8.w, b[nt].x, b[nt].y);
        }

        __half* base = g_Whh + (size_t)d * n_nodes * OUT_F;
#pragma unroll
        for (int nt = 0; nt < 8; nt++) {
            int col = nt * 8 + 2 * t;
            if (r0 < n_nodes) {
                __half2 h = __floats2half2_rn(acc[nt][0] * s0n, acc[nt][1] * s0n);
                *(__half2*)(base + (size_t)r0 * OUT_F + col) = h;
            }
            if (r1 < n_nodes) {
                __half2 h = __floats2half2_rn(acc[nt][2] * s1n, acc[nt][3] * s1n);
                *(__half2*)(base + (size_t)r1 * OUT_F + col) = h;
            }
        }
    }
}

// ---------------------------------------------------------------------------
// Edge bucketing: bucket = dst * 9 + div
// ---------------------------------------------------------------------------
__global__ __launch_bounds__(512)
void hist_kernel(const int* __restrict__ dst, const int* __restrict__ ediv, int E) {
    int e = blockIdx.x * blockDim.x + threadIdx.x;
    if (e >= E) return;
    atomicAdd(&g_hist[dst[e] * NDIV + ediv[e]], 1);
}

__device__ __forceinline__ int block_scan_1024(int v, int tid, int* ws) {
    int lane = tid & 31, wid = tid >> 5;
    int x = v;
#pragma unroll
    for (int o = 1; o < 32; o <<= 1) {
        int y = __shfl_up_sync(0xFFFFFFFFu, x, o);
        if (lane >= o) x += y;
    }
    if (lane == 31) ws[wid] = x;
    __syncthreads();
    if (wid == 0) {
        int s = ws[lane];
#pragma unroll
        for (int o = 1; o < 32; o <<= 1) {
            int y = __shfl_up_sync(0xFFFFFFFFu, s, o);
            if (lane >= o) s += y;
        }
        ws[lane] = s;
    }
    __syncthreads();
    return x + (wid > 0 ? ws[wid - 1] : 0);
}

__global__ __launch_bounds__(1024)
void scan_l1(int NB) {
    __shared__ int ws[32];
    int i = blockIdx.x * 1024 + threadIdx.x;
    int v = (i < NB) ? g_hist[i] : 0;
    int incl = block_scan_1024(v, threadIdx.x, ws);
    if (i <= NB) g_offs[i] = incl - v;
    if (threadIdx.x == 1023) g_bsums[blockIdx.x] = incl;
}

__global__ __launch_bounds__(1024)
void scan_l2(int nblk) {
    __shared__ int ws[32];
    int v = (threadIdx.x < nblk) ? g_bsums[threadIdx.x] : 0;
    int incl = block_scan_1024(v, threadIdx.x, ws);
    if (threadIdx.x < nblk) g_bsums[threadIdx.x] = incl - v;
}

__global__ __launch_bounds__(1024)
void scan_l3(int NB, int E) {
    int i = blockIdx.x * 1024 + threadIdx.x;
    if (i < NB) {
        int o = g_offs[i] + g_bsums[blockIdx.x];
        g_offs[i] = o;
        g_cursor[i] = o;
    }
    if (i == NB) g_offs[NB] = E;
}

__global__ __launch_bounds__(512)
void reorder_kernel(const int* __restrict__ src, const int* __restrict__ dst,
                    const int* __restrict__ ediv, int E) {
    int e = blockIdx.x * blockDim.x + threadIdx.x;
    if (e >= E) return;
    int b = dst[e] * NDIV + ediv[e];
    int pos = atomicAdd(&g_cursor[b], 1);
    g_meta[pos] = src[e];
}

// ---------------------------------------------------------------------------
// Accumulate: one warp per (dst, div). Lane owns 2 output floats in regs.
// 512 threads = 16 warps per block.
// ---------------------------------------------------------------------------
__global__ __launch_bounds__(512)
void accum_kernel(const float* __restrict__ norm,
                  float* __restrict__ out,
                  int n_nodes) {
    int w = blockIdx.x * 16 + (threadIdx.x >> 5);
    int NB = n_nodes * NDIV;
    if (w >= NB) return;
    int lane = threadIdx.x & 31;
    int dn = w / NDIV;
    int d  = w - dn * NDIV;

    int start = __ldg(g_offs + w);
    int end   = __ldg(g_offs + w + 1);

    float2 acc = make_float2(0.f, 0.f);
    // 32-bit offsets: Wh is 115 MB (< 2^27 halves per plane)
    const __half* base = g_Whh + (unsigned)d * (unsigned)(n_nodes * OUT_F) + 2 * lane;
    for (int e = start; e < end; e++) {
        unsigned s = (unsigned)__ldg(g_meta + e);
        __half2 h = *(const __half2*)(base + s * (unsigned)OUT_F);
        float2 f = __half22float2(h);
        acc.x += f.x;
        acc.y += f.y;
    }
    float nr = __ldg(norm + dn);
    float2 o;
    o.x = fmaxf(acc.x * nr, 0.f);
    o.y = fmaxf(acc.y * nr, 0.f);
    *(float2*)(out + (size_t)dn * CAT_F + d * OUT_F + 2 * lane) = o;
}

// ---------------------------------------------------------------------------
extern "C" void kernel_launch(void* const* d_in, const int* in_sizes, int n_in,
                              void* d_out, int out_size) {
    const float* feature = (const float*)d_in[0];
    const float* norm    = (const float*)d_in[1];
    const float* W       = (const float*)d_in[2];
    const int*   src     = (const int*)d_in[3];
    const int*   dst     = (const int*)d_in[4];
    const int*   ediv    = (const int*)d_in[5];
    float* out = (float*)d_out;

    const int n_nodes = in_sizes[1];          // norm is [N,1]
    const int E       = in_sizes[3];          // src is [E]
    const int NB      = n_nodes * NDIV;

    static void* hist_ptr = nullptr;
    static bool init_done = false;
    if (!init_done) {
        cudaFuncSetAttribute(gemm_kernel, cudaFuncAttributeMaxDynamicSharedMemorySize,
                             GEMM_SMEM_BYTES);
        cudaGetSymbolAddress(&hist_ptr, g_hist);
        init_done = true;
    }

    const int eb    = (E + 511) / 512;
    const int nblk1 = (NB + 1023) / 1024;

    // Bucketing first (cheap), so accum directly follows the GEMM and the
    // freshly written Wh tail is still L2-resident for accum's gathers.
    cudaMemsetAsync(hist_ptr, 0, (size_t)NB * sizeof(int), 0);
    hist_kernel<<<eb, 512>>>(dst, ediv, E);
    scan_l1<<<nblk1, 1024>>>(NB);
    scan_l2<<<1, 1024>>>(nblk1);
    scan_l3<<<nblk1 + 1, 1024>>>(NB, E);
    reorder_kernel<<<eb, 512>>>(src, dst, ediv, E);

    dim3 gg((n_nodes + 127) / 128, NDIV / DPB);
    gemm_kernel<<<gg, 256, GEMM_SMEM_BYTES>>>(feature, norm, W, n_nodes);

    int ab = (NB + 15) / 16;
    accum_kernel<<<ab, 512>>>(norm, out, n_nodes);
}

// round 15
// speedup vs baseline: 1.0725x; 1.0725x over previous
#include <cuda_runtime.h>
#include <cuda_fp16.h>
#include <cuda_bf16.h>
#include <cstdint>

#define N_NODES_MAX 100000
#define E_MAX 1600000
#define IN_F 128
#define OUT_F 64
#define NDIV 9
#define CAT_F (NDIV * OUT_F)   // 576
#define DPB 3                  // divisions per block (GEMM)
#define NB_MAX (N_NODES_MAX * NDIV)   // 900000 buckets

// Scratch (static device globals: allowed)
__device__ __half  g_Whh[(size_t)NDIV * N_NODES_MAX * OUT_F];  // 115.2 MB
__device__ int     g_hist[NB_MAX];
__device__ int     g_offs[NB_MAX + 1];
__device__ int     g_cursor[NB_MAX];
__device__ int     g_bsums[1024];
__device__ int     g_meta[E_MAX];      // src node per sorted edge slot

// ---------------------------------------------------------------------------
// bf16 split helpers
// ---------------------------------------------------------------------------
__device__ __forceinline__ unsigned bf16bits(float x) {
    __nv_bfloat16 h = __float2bfloat16(x);
    return (unsigned)__bfloat16_as_ushort(h);
}
__device__ __forceinline__ void split_pair(float x0, float x1,
                                           unsigned& hw, unsigned& lw) {
    unsigned h0 = bf16bits(x0), h1 = bf16bits(x1);
    float r0 = x0 - __uint_as_float(h0 << 16);
    float r1 = x1 - __uint_as_float(h1 << 16);
    unsigned l0 = bf16bits(r0), l1 = bf16bits(r1);
    hw = h0 | (h1 << 16);
    lw = l0 | (l1 << 16);
}

__device__ __forceinline__ void mma_bf16(float c[4],
                                         unsigned a0, unsigned a1, unsigned a2, unsigned a3,
                                         unsigned b0, unsigned b1) {
    asm volatile(
        "mma.sync.aligned.m16n8k16.row.col.f32.bf16.bf16.f32 "
        "{%0,%1,%2,%3}, {%4,%5,%6,%7}, {%8,%9}, {%0,%1,%2,%3};"
        : "+f"(c[0]), "+f"(c[1]), "+f"(c[2]), "+f"(c[3])
        : "r"(a0), "r"(a1), "r"(a2), "r"(a3), "r"(b0), "r"(b1));
}

// Fragment-packed smem layout: per row, k-chunk kc, pair u_local:
// slot = (u&3)*4 + (u>>2) -> hi word; slot+2 -> lo word; word = kc*16+slot.
// ROW_W=144 words: 144%32==16 -> paired-row LDS.128 phases conflict-free.
#define ROW_W 144
#define A_ROWS 64
#define A_WORDS (A_ROWS * ROW_W)
#define B_WORDS (64 * ROW_W)
#define GEMM_SMEM_BYTES ((A_WORDS + B_WORDS) * 4)   // 73,728 B

__device__ __forceinline__ int slot_of(int u_local) {
    return (u_local & 3) * 4 + (u_local >> 2);
}

// Block: 256 threads / 8 warps over a 64row x 64col tile.
// warp w: rows (w&3)*16 .. +16, cols (w>>2)*32 .. +32  (m16 x n32 per warp)
__global__ __launch_bounds__(256, 3)
void gemm_kernel(const float* __restrict__ feature,
                 const float* __restrict__ norm,
                 const float* __restrict__ W,
                 int n_nodes) {
    extern __shared__ unsigned smw[];
    unsigned* As = smw;             // [64][ROW_W]
    unsigned* Bs = smw + A_WORDS;   // [64][ROW_W]

    const int row0 = blockIdx.x * A_ROWS;
    const int d0   = blockIdx.y * DPB;
    const int tid  = threadIdx.x;

    // Load + split A tile once (zero-pad past N). 64 rows x 32 float4.
    for (int i = tid; i < A_ROWS * 32; i += 256) {
        int r = i >> 5, c4 = i & 31;
        float4 v = make_float4(0.f, 0.f, 0.f, 0.f);
        int gr = row0 + r;
        if (gr < n_nodes)
            v = *(const float4*)(feature + (size_t)gr * IN_F + c4 * 4);
        unsigned* rowp = As + r * ROW_W;
        int u0 = c4 * 2;
        unsigned hw, lw;
        split_pair(v.x, v.y, hw, lw);
        int s0 = (u0 >> 3) * 16 + slot_of(u0 & 7);
        rowp[s0] = hw; rowp[s0 + 2] = lw;
        int u1 = u0 + 1;
        split_pair(v.z, v.w, hw, lw);
        int s1 = (u1 >> 3) * 16 + slot_of(u1 & 7);
        rowp[s1] = hw; rowp[s1 + 2] = lw;
    }

    const int warp = tid >> 5, lane = tid & 31;
    const int g = lane >> 2, t = lane & 3;
    const int m0 = (warp & 3) * 16;     // row group within tile
    const int nh = warp >> 2;           // n-half: 0 or 1
    const int r0 = row0 + m0 + g;
    const int r1 = r0 + 8;
    const float s0n = (r0 < n_nodes) ? __ldg(norm + r0) : 0.f;
    const float s1n = (r1 < n_nodes) ? __ldg(norm + r1) : 0.f;

    for (int dd = 0; dd < DPB; dd++) {
        const int d = d0 + dd;
        __syncthreads();
        // Load + split W_d into Bs. 64 rows x 32 float4.
        for (int i = tid; i < 64 * 32; i += 256) {
            int r = i >> 5, c4 = i & 31;
            float4 v = *(const float4*)(W + ((size_t)d * OUT_F + r) * IN_F + c4 * 4);
            unsigned* rowp = Bs + r * ROW_W;
            int u0 = c4 * 2;
            unsigned hw, lw;
            split_pair(v.x, v.y, hw, lw);
            int s0 = (u0 >> 3) * 16 + slot_of(u0 & 7);
            rowp[s0] = hw; rowp[s0 + 2] = lw;
            int u1 = u0 + 1;
            split_pair(v.z, v.w, hw, lw);
            int s1 = (u1 >> 3) * 16 + slot_of(u1 & 7);
            rowp[s1] = hw; rowp[s1 + 2] = lw;
        }
        __syncthreads();

        float acc[4][4];
#pragma unroll
        for (int nt = 0; nt < 4; nt++)
            acc[nt][0] = acc[nt][1] = acc[nt][2] = acc[nt][3] = 0.f;

#pragma unroll
        for (int kc = 0; kc < 8; kc++) {
            const int off = kc * 16 + 4 * t;
            uint4 ag  = *(const uint4*)(As + (m0 + g)     * ROW_W + off);
            uint4 ag8 = *(const uint4*)(As + (m0 + g + 8) * ROW_W + off);
            uint4 b[4];
#pragma unroll
            for (int nt = 0; nt < 4; nt++)
                b[nt] = *(const uint4*)(Bs + (nh * 32 + nt * 8 + g) * ROW_W + off);
            // 3-pass split (hi*hi + hi*lo + lo*hi), pass-outer for MMA ILP
#pragma unroll
            for (int nt = 0; nt < 4; nt++)
                mma_bf16(acc[nt], ag.x, ag8.x, ag.y, ag8.y, b[nt].x, b[nt].y);
#pragma unroll
            for (int nt = 0; nt < 4; nt++)
                mma_bf16(acc[nt], ag.x, ag8.x, ag.y, ag8.y, b[nt].z, b[nt].w);
#pragma unroll
            for (int nt = 0; nt < 4; nt++)
                mma_bf16(acc[nt], ag.z, ag8.z, ag.w, ag8.w, b[nt].x, b[nt].y);
        }

        // Epilogue: scale by norm, store fp16
        __half* base = g_Whh + (size_t)d * n_nodes * OUT_F;
#pragma unroll
        for (int nt = 0; nt < 4; nt++) {
            int col = nh * 32 + nt * 8 + 2 * t;
            if (r0 < n_nodes) {
                __half2 h = __floats2half2_rn(acc[nt][0] * s0n, acc[nt][1] * s0n);
                *(__half2*)(base + (size_t)r0 * OUT_F + col) = h;
            }
            if (r1 < n_nodes) {
                __half2 h = __floats2half2_rn(acc[nt][2] * s1n, acc[nt][3] * s1n);
                *(__half2*)(base + (size_t)r1 * OUT_F + col) = h;
            }
        }
    }
}

// ---------------------------------------------------------------------------
// Edge bucketing: bucket = dst * 9 + div
// ---------------------------------------------------------------------------
__global__ __launch_bounds__(512)
void hist_kernel(const int* __restrict__ dst, const int* __restrict__ ediv, int E) {
    int e = blockIdx.x * blockDim.x + threadIdx.x;
    if (e >= E) return;
    atomicAdd(&g_hist[dst[e] * NDIV + ediv[e]], 1);
}

__device__ __forceinline__ int block_scan_1024(int v, int tid, int* ws) {
    int lane = tid & 31, wid = tid >> 5;
    int x = v;
#pragma unroll
    for (int o = 1; o < 32; o <<= 1) {
        int y = __shfl_up_sync(0xFFFFFFFFu, x, o);
        if (lane >= o) x += y;
    }
    if (lane == 31) ws[wid] = x;
    __syncthreads();
    if (wid == 0) {
        int s = ws[lane];
#pragma unroll
        for (int o = 1; o < 32; o <<= 1) {
            int y = __shfl_up_sync(0xFFFFFFFFu, s, o);
            if (lane >= o) s += y;
        }
        ws[lane] = s;
    }
    __syncthreads();
    return x + (wid > 0 ? ws[wid - 1] : 0);
}

__global__ __launch_bounds__(1024)
void scan_l1(int NB) {
    __shared__ int ws[32];
    int i = blockIdx.x * 1024 + threadIdx.x;
    int v = (i < NB) ? g_hist[i] : 0;
    int incl = block_scan_1024(v, threadIdx.x, ws);
    if (i <= NB) g_offs[i] = incl - v;
    if (threadIdx.x == 1023) g_bsums[blockIdx.x] = incl;
}

__global__ __launch_bounds__(1024)
void scan_l2(int nblk) {
    __shared__ int ws[32];
    int v = (threadIdx.x < nblk) ? g_bsums[threadIdx.x] : 0;
    int incl = block_scan_1024(v, threadIdx.x, ws);
    if (threadIdx.x < nblk) g_bsums[threadIdx.x] = incl - v;
}

__global__ __launch_bounds__(1024)
void scan_l3(int NB, int E) {
    int i = blockIdx.x * 1024 + threadIdx.x;
    if (i < NB) {
        int o = g_offs[i] + g_bsums[blockIdx.x];
        g_offs[i] = o;
        g_cursor[i] = o;
    }
    if (i == NB) g_offs[NB] = E;
}

__global__ __launch_bounds__(512)
void reorder_kernel(const int* __restrict__ src, const int* __restrict__ dst,
                    const int* __restrict__ ediv, int E) {
    int e = blockIdx.x * blockDim.x + threadIdx.x;
    if (e >= E) return;
    int b = dst[e] * NDIV + ediv[e];
    int pos = atomicAdd(&g_cursor[b], 1);
    g_meta[pos] = src[e];
}

// ---------------------------------------------------------------------------
// Accumulate: one warp per (dst, div). Lane owns 2 output floats in regs.
// ---------------------------------------------------------------------------
__global__ __launch_bounds__(256)
void accum_kernel(const float* __restrict__ norm,
                  float* __restrict__ out,
                  int n_nodes) {
    int w = blockIdx.x * 8 + (threadIdx.x >> 5);
    int NB = n_nodes * NDIV;
    if (w >= NB) return;
    int lane = threadIdx.x & 31;
    int dn = w / NDIV;
    int d  = w - dn * NDIV;

    int start = __ldg(g_offs + w);
    int end   = __ldg(g_offs + w + 1);

    float2 acc = make_float2(0.f, 0.f);
    const __half* base = g_Whh + (unsigned)d * (unsigned)(n_nodes * OUT_F) + 2 * lane;
    for (int e = start; e < end; e++) {
        unsigned s = (unsigned)__ldg(g_meta + e);
        __half2 h = *(const __half2*)(base + s * (unsigned)OUT_F);
        float2 f = __half22float2(h);
        acc.x += f.x;
        acc.y += f.y;
    }
    float nr = __ldg(norm + dn);
    float2 o;
    o.x = fmaxf(acc.x * nr, 0.f);
    o.y = fmaxf(acc.y * nr, 0.f);
    *(float2*)(out + (size_t)dn * CAT_F + d * OUT_F + 2 * lane) = o;
}

// ---------------------------------------------------------------------------
extern "C" void kernel_launch(void* const* d_in, const int* in_sizes, int n_in,
                              void* d_out, int out_size) {
    const float* feature = (const float*)d_in[0];
    const float* norm    = (const float*)d_in[1];
    const float* W       = (const float*)d_in[2];
    const int*   src     = (const int*)d_in[3];
    const int*   dst     = (const int*)d_in[4];
    const int*   ediv    = (const int*)d_in[5];
    float* out = (float*)d_out;

    const int n_nodes = in_sizes[1];          // norm is [N,1]
    const int E       = in_sizes[3];          // src is [E]
    const int NB      = n_nodes * NDIV;

    static void* hist_ptr = nullptr;
    static bool init_done = false;
    if (!init_done) {
        cudaFuncSetAttribute(gemm_kernel, cudaFuncAttributeMaxDynamicSharedMemorySize,
                             GEMM_SMEM_BYTES);
        cudaGetSymbolAddress(&hist_ptr, g_hist);
        init_done = true;
    }

    const int eb    = (E + 511) / 512;
    const int nblk1 = (NB + 1023) / 1024;

    // R6-proven order: GEMM first, then bucketing (its small outputs stay
    // L2-hot for accum), then accum.
    cudaMemsetAsync(hist_ptr, 0, (size_t)NB * sizeof(int), 0);

    dim3 gg((n_nodes + A_ROWS - 1) / A_ROWS, NDIV / DPB);
    gemm_kernel<<<gg, 256, GEMM_SMEM_BYTES>>>(feature, norm, W, n_nodes);

    hist_kernel<<<eb, 512>>>(dst, ediv, E);
    scan_l1<<<nblk1, 1024>>>(NB);
    scan_l2<<<1, 1024>>>(nblk1);
    scan_l3<<<nblk1 + 1, 1024>>>(NB, E);
    reorder_kernel<<<eb, 512>>>(src, dst, ediv, E);

    int ab = (NB + 7) / 8;
    accum_kernel<<<ab, 256>>>(norm, out, n_nodes);
}